// round 1
// baseline (speedup 1.0000x reference)
#include <cuda_runtime.h>
#include <math.h>

// ---------------- fixed CT geometry ----------------
#define IMG   512
#define NDET  768
#define NV    360
#define GLEN  (2*NDET-1)          // 1535 ramp taps

#define PIXf  0.7433f
#define DSOd  595.0
#define DSDd  (595.0 + 490.6)     // 1085.6
#define DETd  1.2858
// DGAMMA = DETd/DSDd  (rad per detector bin)

// ---------------- device scratch (no allocations allowed) ----------------
__device__ float  g_tab[GLEN];            // ramp kernel * DGAMMA * (2pi/NV)
__device__ float2 cs_tab[NV];             // (cos beta, sin beta)
__device__ float4 q_pack[NV * NDET];      // (q0[d], q0[d+1], q1[d], q1[d+1])

// ---------------- init: ramp kernel + view angles (double precision) ------
__global__ void init_kernel() {
    int i = blockIdx.x * blockDim.x + threadIdx.x;
    const double dg = DETd / DSDd;
    if (i < GLEN) {
        int n = i - (NDET - 1);
        double g = 0.0;
        if (n == 0) {
            g = 1.0 / (8.0 * dg * dg);
        } else if (n & 1) {                 // odd taps only; even taps are 0
            double s = sin((double)n * dg);
            double d = M_PI * s;
            g = -0.5 / (d * d);
        }
        // fold q *= DGAMMA  and final *= 2*pi/NV  into the kernel
        g_tab[i] = (float)(g * dg * (2.0 * M_PI / (double)NV));
    }
    if (i < NV) {
        double beta = (double)i * (2.0 * M_PI / (double)NV);
        cs_tab[i] = make_float2((float)cos(beta), (float)sin(beta));
    }
}

// ---------------- filtering: cosine weight + odd-tap ramp convolution -----
// One block per view, 768 threads; both batches handled together so the
// float4 interleaved pack can be written directly.
__global__ void __launch_bounds__(NDET) filter_kernel(const float* __restrict__ proj) {
    __shared__ float p1s[2][NDET];
    __shared__ float gs[GLEN];
    __shared__ float qs[2][NDET];

    const int v = blockIdx.x;
    const int t = threadIdx.x;

    for (int i = t; i < GLEN; i += NDET) gs[i] = g_tab[i];

    const float dgf = (float)(DETd / DSDd);
    float gam = ((float)t - 383.5f) * dgf;
    float cw  = 595.0f * cosf(gam);                  // DSO * cos(gamma)
    p1s[0][t] = proj[(0 * NV + v) * NDET + t] * cw;
    p1s[1][t] = proj[(1 * NV + v) * NDET + t] * cw;
    __syncthreads();

    // q[t] = p1[t]*g(0) + sum over k with (t-k) odd of p1[k]*g(t-k)
    float a0 = p1s[0][t] * gs[NDET - 1];
    float a1 = p1s[1][t] * gs[NDET - 1];
    const int par = (t + 1) & 1;                     // k parity making t-k odd
#pragma unroll 4
    for (int k = par; k < NDET; k += 2) {
        float gv = gs[t - k + (NDET - 1)];
        a0 = fmaf(p1s[0][k], gv, a0);
        a1 = fmaf(p1s[1][k], gv, a1);
    }
    qs[0][t] = a0;
    qs[1][t] = a1;
    __syncthreads();

    int dn = min(t + 1, NDET - 1);                   // i0 <= 766, pad last pair
    q_pack[v * NDET + t] = make_float4(qs[0][t], qs[0][dn], qs[1][t], qs[1][dn]);
}

// ---------------- backprojection: 1 thread = 1 pixel, both batches --------
__global__ void __launch_bounds__(256) bp_kernel(float* __restrict__ out) {
    __shared__ float2 cs_s[NV];
    const int tid = threadIdx.y * 16 + threadIdx.x;
    for (int s = tid; s < NV; s += 256) cs_s[s] = cs_tab[s];
    __syncthreads();

    const int j = (blockIdx.x << 4) + threadIdx.x;   // column -> x
    const int i = (blockIdx.y << 4) + threadIdx.y;   // row    -> y

    const float x = ((float)j - 255.5f) * PIXf;
    const float y = ((float)i - 255.5f) * PIXf;
    const float DSOf = 595.0f;
    const float R2 = fmaf(x, x, fmaf(y, y, DSOf * DSOf));
    const float INV_DG = (float)(DSDd / DETd);       // 1/DGAMMA

    float acc0 = 0.0f, acc1 = 0.0f;

#pragma unroll 4
    for (int v = 0; v < NV; ++v) {
        float2 cs = cs_s[v];
        float u  = fmaf(cs.x, x, cs.y * y);          // cb*x + sb*y
        float cr = fmaf(cs.y, x, -cs.x * y);         // sb*x - cb*y
        float dt = DSOf - u;                         // > 0 for all FOV pixels
        float L2 = fmaf(-2.0f * DSOf, u, R2);        // vx^2 + vy^2
        float tq = __fdividef(cr, dt);
        float g  = fmaf(atanf(tq), INV_DG, 383.5f);  // detector index
        float fg = floorf(g);
        int   i0 = (int)fg;
        i0 = max(0, min(i0, NDET - 2));
        float w  = g - fg;
        float wl = (g >= 0.0f && g <= 767.0f) ? __fdividef(1.0f, L2) : 0.0f;

        float4 q = q_pack[v * NDET + i0];            // one LDG.128 per view
        acc0 = fmaf(fmaf(w, q.y - q.x, q.x), wl, acc0);
        acc1 = fmaf(fmaf(w, q.w - q.z, q.z), wl, acc1);
    }

    out[(size_t)i * IMG + j] = acc0;
    out[(size_t)IMG * IMG + (size_t)i * IMG + j] = acc1;
}

// ---------------- entry point ----------------
extern "C" void kernel_launch(void* const* d_in, const int* in_sizes, int n_in,
                              void* d_out, int out_size) {
    (void)in_sizes; (void)n_in; (void)out_size;
    const float* proj = (const float*)d_in[0];   // [2, 360, 768] f32
    float* out = (float*)d_out;                  // [2, 512, 512] f32

    init_kernel<<<2, 1024>>>();
    filter_kernel<<<NV, NDET>>>(proj);
    bp_kernel<<<dim3(IMG / 16, IMG / 16), dim3(16, 16)>>>(out);
}

// round 2
// speedup vs baseline: 1.1364x; 1.1364x over previous
#include <cuda_runtime.h>
#include <math.h>

// ---------------- fixed CT geometry ----------------
#define IMG   512
#define NDET  768
#define NV    360
#define GLEN  (2*NDET-1)          // 1535 ramp taps

#define PIXd  0.7433
#define DSOd  595.0
#define DSDd  1085.6              // 595.0 + 490.6
#define DETd  1.2858
#define DGd   (DETd / DSDd)       // equiangular pitch (rad/bin)
#define SCALEd (DGd * 2.0 * M_PI / 360.0)   // fold q*=DGAMMA and *=2pi/NV

// ---------------- device scratch (no allocations allowed) ----------------
__device__ float2 cs_tab[NV];             // (cos beta, sin beta), double-accurate
__device__ float4 q_pack[NV * NDET];      // (q0[d], q0[d+1], q1[d], q1[d+1])

// ---------------- filtering: cosine weight + odd-tap ramp convolution -----
// One block per view, 768 threads. Computes the ramp table in smem (fp32),
// thread 0 also produces this view's (cos,sin) in double via sincospi.
__global__ void __launch_bounds__(NDET) filter_kernel(const float* __restrict__ proj) {
    __shared__ float2 p2[NDET];           // (batch0, batch1) cosine-weighted
    __shared__ float  gs[GLEN];
    __shared__ float2 q2[NDET];

    const int v = blockIdx.x;
    const int t = threadIdx.x;

    if (t == 0) {                          // exact view angle, hidden under conv
        double sb, cb;
        sincospi((double)v / 180.0, &sb, &cb);
        cs_tab[v] = make_float2((float)cb, (float)sb);
    }

    // ramp kernel (only odd taps nonzero + center), fp32 is plenty (2e-7 rel)
    for (int i = t; i < GLEN; i += NDET) {
        int n = i - (NDET - 1);
        float g;
        if (n == 0) {
            g = (float)(SCALEd / (8.0 * DGd * DGd));
        } else if (n & 1) {
            float s = sinf((float)n * (float)DGd) * (float)M_PI;
            g = (float)(-0.5 * SCALEd) / (s * s);
        } else {
            g = 0.0f;
        }
        gs[i] = g;
    }

    float gam = ((float)t - 383.5f) * (float)DGd;
    float cw  = 595.0f * cosf(gam);                  // DSO * cos(gamma)
    p2[t] = make_float2(proj[(0 * NV + v) * NDET + t] * cw,
                        proj[(1 * NV + v) * NDET + t] * cw);
    __syncthreads();

    // q[t] = p[t]*g(0) + sum over k with (t-k) odd of p[k]*g(t-k)
    float2 pc = p2[t];
    float g0  = gs[NDET - 1];
    float a0 = pc.x * g0;
    float a1 = pc.y * g0;
    const int k0 = (t + 1) & 1;                      // k parity making t-k odd
#pragma unroll 8
    for (int k = k0; k < NDET; k += 2) {
        float gv = gs[t - k + (NDET - 1)];
        float2 p = p2[k];                            // one broadcast LDS.64
        a0 = fmaf(p.x, gv, a0);
        a1 = fmaf(p.y, gv, a1);
    }
    q2[t] = make_float2(a0, a1);
    __syncthreads();

    int dn = min(t + 1, NDET - 1);                   // pad last pair (i0 <= 766)
    float2 qa = q2[t], qb = q2[dn];
    q_pack[v * NDET + t] = make_float4(qa.x, qb.x, qa.y, qb.y);
}

// ---------------- backprojection: 1 thread = 2 pixels (y-paired), 2 batches
// atan replaced by degree-11 odd minimax poly on [-0.52, 0.52]
// (|cr/dt| <= 0.506 for every FOV pixel), 1/DGAMMA folded into coefficients.
__global__ void __launch_bounds__(256) bp_kernel(float* __restrict__ out) {
    __shared__ float2 cs_s[NV];
    const int tid = threadIdx.y * 16 + threadIdx.x;
    for (int s = tid; s < NV; s += 256) cs_s[s] = cs_tab[s];
    __syncthreads();

    const int j = (blockIdx.x << 4) + threadIdx.x;   // column -> x
    const int i = (blockIdx.y << 5) + threadIdx.y;   // rows i and i+16

    const float x  = ((float)j - 255.5f) * (float)PIXd;
    const float y  = ((float)i - 255.5f) * (float)PIXd;
    const float DY = 16.0f * (float)PIXd;
    const float yb = y + DY;
    const float DSOf = 595.0f;
    const float R2a = fmaf(x, x, fmaf(y,  y,  DSOf * DSOf));
    const float R2b = fmaf(x, x, fmaf(yb, yb, DSOf * DSOf));

    // minimax atan coefficients * (1/DGAMMA), compile-time folded in double
    const float B0 = (float)( 0.99999965 * (DSDd / DETd));
    const float B1 = (float)(-0.33332840 * (DSDd / DETd));
    const float B2 = (float)( 0.19985310 * (DSDd / DETd));
    const float B3 = (float)(-0.14090870 * (DSDd / DETd));
    const float B4 = (float)( 0.09813380 * (DSDd / DETd));
    const float B5 = (float)(-0.04615630 * (DSDd / DETd));

    float acc00 = 0.0f, acc01 = 0.0f;                // pixel A, batches 0/1
    float acc10 = 0.0f, acc11 = 0.0f;                // pixel B, batches 0/1

#pragma unroll 4
    for (int v = 0; v < NV; ++v) {
        float2 cs = cs_s[v];
        float u   = fmaf(cs.x, x,  cs.y * y);        // cb*x + sb*y
        float cr  = fmaf(cs.y, x, -cs.x * y);        // sb*x - cb*y
        float u2  = fmaf(cs.y,  DY, u);              // incremental for y+DY
        float cr2 = fmaf(-cs.x, DY, cr);

        // ---- pixel A ----
        {
            float dt = DSOf - u;
            float L2 = fmaf(-2.0f * DSOf, u, R2a);
            float tq = __fdividef(cr, dt);
            float s2 = tq * tq;
            float p  = fmaf(B5, s2, B4);
            p = fmaf(p, s2, B3);
            p = fmaf(p, s2, B2);
            p = fmaf(p, s2, B1);
            p = fmaf(p, s2, B0);
            float g  = fmaf(tq, p, 383.5f);
            float fg = floorf(g);
            int   i0 = min(max((int)fg, 0), NDET - 2);
            float w  = g - fg;
            float wl = (g >= 0.0f && g <= 767.0f) ? __fdividef(1.0f, L2) : 0.0f;
            float4 q = q_pack[v * NDET + i0];        // one LDG.128
            acc00 = fmaf(fmaf(w, q.y - q.x, q.x), wl, acc00);
            acc01 = fmaf(fmaf(w, q.w - q.z, q.z), wl, acc01);
        }
        // ---- pixel B (y + 16 rows) ----
        {
            float dt = DSOf - u2;
            float L2 = fmaf(-2.0f * DSOf, u2, R2b);
            float tq = __fdividef(cr2, dt);
            float s2 = tq * tq;
            float p  = fmaf(B5, s2, B4);
            p = fmaf(p, s2, B3);
            p = fmaf(p, s2, B2);
            p = fmaf(p, s2, B1);
            p = fmaf(p, s2, B0);
            float g  = fmaf(tq, p, 383.5f);
            float fg = floorf(g);
            int   i0 = min(max((int)fg, 0), NDET - 2);
            float w  = g - fg;
            float wl = (g >= 0.0f && g <= 767.0f) ? __fdividef(1.0f, L2) : 0.0f;
            float4 q = q_pack[v * NDET + i0];
            acc10 = fmaf(fmaf(w, q.y - q.x, q.x), wl, acc10);
            acc11 = fmaf(fmaf(w, q.w - q.z, q.z), wl, acc11);
        }
    }

    out[i * IMG + j]                       = acc00;
    out[(i + 16) * IMG + j]                = acc10;
    out[IMG * IMG + i * IMG + j]           = acc01;
    out[IMG * IMG + (i + 16) * IMG + j]    = acc11;
}

// ---------------- entry point ----------------
extern "C" void kernel_launch(void* const* d_in, const int* in_sizes, int n_in,
                              void* d_out, int out_size) {
    (void)in_sizes; (void)n_in; (void)out_size;
    const float* proj = (const float*)d_in[0];   // [2, 360, 768] f32
    float* out = (float*)d_out;                  // [2, 512, 512] f32

    filter_kernel<<<NV, NDET>>>(proj);
    bp_kernel<<<dim3(IMG / 16, IMG / 32), dim3(16, 16)>>>(out);
}

// round 3
// speedup vs baseline: 1.3481x; 1.1863x over previous
#include <cuda_runtime.h>
#include <math.h>

// ---------------- fixed CT geometry ----------------
#define IMG   512
#define NDET  768
#define NV    360
#define GLEN  (2*NDET-1)          // 1535 ramp taps

#define PIXd  0.7433
#define DSOd  595.0
#define DSDd  1085.6              // 595.0 + 490.6
#define DETd  1.2858
#define DGd   (DETd / DSDd)       // equiangular pitch (rad/bin)
#define INVDGd (DSDd / DETd)
#define SCALEd (DGd * 2.0 * M_PI / 360.0)   // fold q*=DGAMMA and *=2pi/NV

// ---------------- device scratch (no allocations allowed) ----------------
__device__ float2 cs_tab[NV];             // (cos beta, sin beta), double-accurate
__device__ float4 q_pack[NV * NDET];      // (q0[d], dq0[d], q1[d], dq1[d])

// ---------------- filtering: cosine weight + odd-tap ramp convolution -----
__global__ void __launch_bounds__(NDET) filter_kernel(const float* __restrict__ proj) {
    __shared__ float2 p2[NDET];           // (batch0, batch1) cosine-weighted
    __shared__ float  gs[GLEN];
    __shared__ float2 q2[NDET];

    const int v = blockIdx.x;
    const int t = threadIdx.x;

    if (t == 0) {                          // exact view angle, hidden under conv
        double sb, cb;
        sincospi((double)v / 180.0, &sb, &cb);
        cs_tab[v] = make_float2((float)cb, (float)sb);
    }

    // ramp kernel (only odd taps nonzero + center), fp32 is plenty (2e-7 rel)
    for (int i = t; i < GLEN; i += NDET) {
        int n = i - (NDET - 1);
        float g;
        if (n == 0) {
            g = (float)(SCALEd / (8.0 * DGd * DGd));
        } else if (n & 1) {
            float s = sinf((float)n * (float)DGd) * (float)M_PI;
            g = (float)(-0.5 * SCALEd) / (s * s);
        } else {
            g = 0.0f;
        }
        gs[i] = g;
    }

    float gam = ((float)t - 383.5f) * (float)DGd;
    float cw  = 595.0f * cosf(gam);                  // DSO * cos(gamma)
    p2[t] = make_float2(proj[(0 * NV + v) * NDET + t] * cw,
                        proj[(1 * NV + v) * NDET + t] * cw);
    __syncthreads();

    // q[t] = p[t]*g(0) + sum over k with (t-k) odd of p[k]*g(t-k)
    float2 pc = p2[t];
    float g0  = gs[NDET - 1];
    float a0 = pc.x * g0;
    float a1 = pc.y * g0;
    const int k0 = (t + 1) & 1;                      // k parity making t-k odd
#pragma unroll 8
    for (int k = k0; k < NDET; k += 2) {
        float gv = gs[t - k + (NDET - 1)];
        float2 p = p2[k];                            // one broadcast LDS.64
        a0 = fmaf(p.x, gv, a0);
        a1 = fmaf(p.y, gv, a1);
    }
    q2[t] = make_float2(a0, a1);
    __syncthreads();

    int dn = min(t + 1, NDET - 1);                   // last pair: delta = 0
    float2 qa = q2[t], qb = q2[dn];
    q_pack[v * NDET + t] = make_float4(qa.x, qb.x - qa.x, qa.y, qb.y - qa.y);
}

// ---------------- backprojection: 1 thread = 1 pixel, both batches --------
// atan(t) = t*P(t^2): degree-11 Chebyshev-exact on |t|<=0.5059 (covers all
// FOV pixels; max |cr/dt| = 0.50586 at corners). Truncation err 1.25e-9 rad.
// 1/DGAMMA folded into coefficients at compile time.
__global__ void __launch_bounds__(256, 7) bp_kernel(float* __restrict__ out) {
    __shared__ float2 cs_s[NV];
    const int tid = threadIdx.y * 16 + threadIdx.x;
    for (int s = tid; s < NV; s += 256) cs_s[s] = cs_tab[s];
    __syncthreads();

    const int j = (blockIdx.x << 4) + threadIdx.x;   // column -> x
    const int i = (blockIdx.y << 4) + threadIdx.y;   // row    -> y

    const float x = ((float)j - 255.5f) * (float)PIXd;
    const float y = ((float)i - 255.5f) * (float)PIXd;
    const float DSOf = 595.0f;
    const float R2 = fmaf(x, x, fmaf(y, y, DSOf * DSOf));

    // Chebyshev-derived atan coefficients * (1/DGAMMA)
    const float B0 = (float)( 1.00000000 * INVDGd);
    const float B1 = (float)(-0.33332973 * INVDGd);
    const float B2 = (float)( 0.19987850 * INVDGd);
    const float B3 = (float)(-0.14115230 * INVDGd);
    const float B4 = (float)( 0.09916330 * INVDGd);
    const float B5 = (float)(-0.04772060 * INVDGd);

    float acc0 = 0.0f, acc1 = 0.0f;

#pragma unroll 4
    for (int v = 0; v < NV; ++v) {
        float2 cs = cs_s[v];
        float u  = fmaf(cs.x, x,  cs.y * y);         // cb*x + sb*y
        float cr = fmaf(cs.y, x, -cs.x * y);         // sb*x - cb*y
        float dt = DSOf - u;                         // > 0 for all FOV pixels
        float L2 = fmaf(-2.0f * DSOf, u, R2);        // vx^2 + vy^2
        float tq = __fdividef(cr, dt);
        float s2 = tq * tq;
        float p  = fmaf(B5, s2, B4);
        p = fmaf(p, s2, B3);
        p = fmaf(p, s2, B2);
        p = fmaf(p, s2, B1);
        p = fmaf(p, s2, B0);
        float g  = fmaf(tq, p, 383.5f);              // detector index
        float fg = floorf(g);
        int   i0 = min(max((int)fg, 0), NDET - 2);
        float w  = g - fg;
        float wl = (g >= 0.0f && g <= 767.0f) ? __fdividef(1.0f, L2) : 0.0f;

        float4 q = q_pack[v * NDET + i0];            // one LDG.128 per view
        acc0 = fmaf(fmaf(w, q.y, q.x), wl, acc0);    // q.y/q.w are pre-diffed
        acc1 = fmaf(fmaf(w, q.w, q.z), wl, acc1);
    }

    out[i * IMG + j]             = acc0;
    out[IMG * IMG + i * IMG + j] = acc1;
}

// ---------------- entry point ----------------
extern "C" void kernel_launch(void* const* d_in, const int* in_sizes, int n_in,
                              void* d_out, int out_size) {
    (void)in_sizes; (void)n_in; (void)out_size;
    const float* proj = (const float*)d_in[0];   // [2, 360, 768] f32
    float* out = (float*)d_out;                  // [2, 512, 512] f32

    filter_kernel<<<NV, NDET>>>(proj);
    bp_kernel<<<dim3(IMG / 16, IMG / 16), dim3(16, 16)>>>(out);
}